// round 1
// baseline (speedup 1.0000x reference)
#include <cuda_runtime.h>
#include <float.h>
#include <math.h>

#define S_ROWS 2048
#define T_ROWS 50000
#define DDIM   1024
#define KNN    4
#define BM     128
#define BN     128
#define BK     16
#define AST    132          // padded smem stride (conflict avoidance)
#define NT     ((T_ROWS + BN - 1) / BN)   // 391
#define MT     (S_ROWS / BM)              // 16

// Scratch (module-scope device arrays: allowed; no runtime allocation)
__device__ float g_invn[T_ROWS];
__device__ float g_pv[S_ROWS * NT * KNN];   // ~12.8 MB
__device__ int   g_pi[S_ROWS * NT * KNN];   // ~12.8 MB

// Total order matching jax.lax.top_k: value desc, ties -> lower index first
__device__ __forceinline__ bool better(float v, int i, float v2, int i2) {
    return (v > v2) || (v == v2 && i < i2);
}

__device__ __forceinline__ void ins4(float v, int i, float tv[KNN], int ti[KNN]) {
    if (!better(v, i, tv[KNN - 1], ti[KNN - 1])) return;
    tv[KNN - 1] = v; ti[KNN - 1] = i;
#pragma unroll
    for (int q = KNN - 1; q > 0; --q) {
        if (better(tv[q], ti[q], tv[q - 1], ti[q - 1])) {
            float fv = tv[q]; tv[q] = tv[q - 1]; tv[q - 1] = fv;
            int fi = ti[q]; ti[q] = ti[q - 1]; ti[q - 1] = fi;
        }
    }
}

// ---------------------------------------------------------------------------
// Kernel 1: per-target-row inverse norms
// ---------------------------------------------------------------------------
__global__ void row_norm_kernel(const float* __restrict__ Bt) {
    int t = blockIdx.x;
    const float4* row = reinterpret_cast<const float4*>(Bt + (size_t)t * DDIM);
    float s = 0.f;
#pragma unroll
    for (int i = 0; i < 2; ++i) {
        float4 v = row[threadIdx.x + i * 128];
        s += v.x * v.x + v.y * v.y + v.z * v.z + v.w * v.w;
    }
#pragma unroll
    for (int o = 16; o > 0; o >>= 1) s += __shfl_down_sync(0xffffffffu, s, o);
    __shared__ float ws[4];
    int lane = threadIdx.x & 31, w = threadIdx.x >> 5;
    if (lane == 0) ws[w] = s;
    __syncthreads();
    if (threadIdx.x == 0) {
        float tot = ws[0] + ws[1] + ws[2] + ws[3];
        g_invn[t] = 1.f / fmaxf(sqrtf(tot), 1e-8f);
    }
}

// ---------------------------------------------------------------------------
// Kernel 2: fp32 SIMT GEMM (128x128x1024) + fused per-tile top-4 epilogue
// sims[m][n] = dot(src[m], tgt[n]) * invnorm(tgt[n])
// ---------------------------------------------------------------------------
__global__ __launch_bounds__(256, 2)
void gemm_topk_kernel(const float* __restrict__ A, const float* __restrict__ Bt) {
    __shared__ __align__(16) float smem[4 * BK * AST];   // 33792 B
    float* sA0 = smem;                    // 2 buffers A
    float* sB0 = smem + 2 * BK * AST;     // 2 buffers B

    const int tid = threadIdx.x;
    const int tx = tid & 15, ty = tid >> 4;
    const int m0 = blockIdx.y * BM;
    const int n0 = blockIdx.x * BN;

    // loader mapping: 512 float4 per tile / 256 threads = 2 each
    const int lrow = tid >> 2;            // 0..63
    const int lk4  = (tid & 3) << 2;      // 0,4,8,12

    const float* Abase  = A  + (size_t)(m0 + lrow) * DDIM + lk4;
    const int tr0 = n0 + lrow;
    const int tr1 = tr0 + 64;
    const float* Bbase0 = Bt + (size_t)tr0 * DDIM + lk4;
    const float* Bbase1 = Bt + (size_t)tr1 * DDIM + lk4;
    const bool bok0 = tr0 < T_ROWS;
    const bool bok1 = tr1 < T_ROWS;

    float acc[8][8];
#pragma unroll
    for (int i = 0; i < 8; ++i)
#pragma unroll
        for (int j = 0; j < 8; ++j) acc[i][j] = 0.f;

    const float4 z4 = make_float4(0.f, 0.f, 0.f, 0.f);
    float4 ra0, ra1, rb0, rb1;

    // prologue: tile 0
    ra0 = *reinterpret_cast<const float4*>(Abase);
    ra1 = *reinterpret_cast<const float4*>(Abase + 64 * DDIM);
    rb0 = bok0 ? *reinterpret_cast<const float4*>(Bbase0) : z4;
    rb1 = bok1 ? *reinterpret_cast<const float4*>(Bbase1) : z4;

    int buf = 0;
    {
        float* a = sA0;
        float* b = sB0;
        a[(lk4 + 0) * AST + lrow] = ra0.x;  a[(lk4 + 1) * AST + lrow] = ra0.y;
        a[(lk4 + 2) * AST + lrow] = ra0.z;  a[(lk4 + 3) * AST + lrow] = ra0.w;
        a[(lk4 + 0) * AST + lrow + 64] = ra1.x;  a[(lk4 + 1) * AST + lrow + 64] = ra1.y;
        a[(lk4 + 2) * AST + lrow + 64] = ra1.z;  a[(lk4 + 3) * AST + lrow + 64] = ra1.w;
        b[(lk4 + 0) * AST + lrow] = rb0.x;  b[(lk4 + 1) * AST + lrow] = rb0.y;
        b[(lk4 + 2) * AST + lrow] = rb0.z;  b[(lk4 + 3) * AST + lrow] = rb0.w;
        b[(lk4 + 0) * AST + lrow + 64] = rb1.x;  b[(lk4 + 1) * AST + lrow + 64] = rb1.y;
        b[(lk4 + 2) * AST + lrow + 64] = rb1.z;  b[(lk4 + 3) * AST + lrow + 64] = rb1.w;
    }
    __syncthreads();

#pragma unroll 1
    for (int kt = 0; kt < DDIM / BK; ++kt) {
        const int kn = (kt + 1) * BK;
        const bool more = (kt + 1) < (DDIM / BK);
        if (more) {
            ra0 = *reinterpret_cast<const float4*>(Abase + kn);
            ra1 = *reinterpret_cast<const float4*>(Abase + 64 * DDIM + kn);
            rb0 = bok0 ? *reinterpret_cast<const float4*>(Bbase0 + kn) : z4;
            rb1 = bok1 ? *reinterpret_cast<const float4*>(Bbase1 + kn) : z4;
        }

        const float* sAc = sA0 + buf * (BK * AST);
        const float* sBc = sB0 + buf * (BK * AST);
#pragma unroll
        for (int k = 0; k < BK; ++k) {
            float4 a0 = *reinterpret_cast<const float4*>(sAc + k * AST + (ty << 3));
            float4 a1 = *reinterpret_cast<const float4*>(sAc + k * AST + (ty << 3) + 4);
            float4 b0 = *reinterpret_cast<const float4*>(sBc + k * AST + (tx << 3));
            float4 b1 = *reinterpret_cast<const float4*>(sBc + k * AST + (tx << 3) + 4);
            float av[8] = {a0.x, a0.y, a0.z, a0.w, a1.x, a1.y, a1.z, a1.w};
            float bv[8] = {b0.x, b0.y, b0.z, b0.w, b1.x, b1.y, b1.z, b1.w};
#pragma unroll
            for (int i = 0; i < 8; ++i)
#pragma unroll
                for (int j = 0; j < 8; ++j)
                    acc[i][j] = fmaf(av[i], bv[j], acc[i][j]);
        }

        if (more) {
            const int nb = buf ^ 1;
            float* a = sA0 + nb * (BK * AST);
            float* b = sB0 + nb * (BK * AST);
            a[(lk4 + 0) * AST + lrow] = ra0.x;  a[(lk4 + 1) * AST + lrow] = ra0.y;
            a[(lk4 + 2) * AST + lrow] = ra0.z;  a[(lk4 + 3) * AST + lrow] = ra0.w;
            a[(lk4 + 0) * AST + lrow + 64] = ra1.x;  a[(lk4 + 1) * AST + lrow + 64] = ra1.y;
            a[(lk4 + 2) * AST + lrow + 64] = ra1.z;  a[(lk4 + 3) * AST + lrow + 64] = ra1.w;
            b[(lk4 + 0) * AST + lrow] = rb0.x;  b[(lk4 + 1) * AST + lrow] = rb0.y;
            b[(lk4 + 2) * AST + lrow] = rb0.z;  b[(lk4 + 3) * AST + lrow] = rb0.w;
            b[(lk4 + 0) * AST + lrow + 64] = rb1.x;  b[(lk4 + 1) * AST + lrow + 64] = rb1.y;
            b[(lk4 + 2) * AST + lrow + 64] = rb1.z;  b[(lk4 + 3) * AST + lrow + 64] = rb1.w;
        }
        __syncthreads();
        buf ^= 1;
    }

    // ---- epilogue: scale by inv-norm, per-row top-4 within this 128-col tile
    const int nbase = n0 + (tx << 3);
    float inv[8];
#pragma unroll
    for (int j = 0; j < 8; ++j)
        inv[j] = (nbase + j < T_ROWS) ? g_invn[nbase + j] : 0.f;

    float* sims = smem;   // reuse: 64 rows x stride 129 = 8256 floats <= 8448

    for (int pass = 0; pass < 2; ++pass) {
        __syncthreads();
        if ((ty >> 3) == pass) {
            const int rb = (ty & 7) << 3;
#pragma unroll
            for (int i = 0; i < 8; ++i)
#pragma unroll
                for (int j = 0; j < 8; ++j) {
                    float v = (nbase + j < T_ROWS) ? acc[i][j] * inv[j] : -FLT_MAX;
                    sims[(rb + i) * 129 + (tx << 3) + j] = v;
                }
        }
        __syncthreads();
        if (tid < 64) {
            float tv[KNN] = {-FLT_MAX, -FLT_MAX, -FLT_MAX, -FLT_MAX};
            int   ti4[KNN] = {0x7fffffff, 0x7fffffff, 0x7fffffff, 0x7fffffff};
            const float* rowp = sims + tid * 129;
            for (int c = 0; c < 128; ++c) ins4(rowp[c], n0 + c, tv, ti4);
            const int m = m0 + (pass << 6) + tid;
            const int base = (m * NT + blockIdx.x) * KNN;
#pragma unroll
            for (int q = 0; q < KNN; ++q) {
                g_pv[base + q] = tv[q];
                g_pi[base + q] = ti4[q];
            }
        }
    }
}

// ---------------------------------------------------------------------------
// Kernel 3: merge per-tile top-4 lists -> global top-4; gather + mean
// ---------------------------------------------------------------------------
__global__ void merge_kernel(const float* __restrict__ Bt, float* __restrict__ out) {
    const int s = blockIdx.x;
    const int tid = threadIdx.x;
    const int C = NT * KNN;   // 1564 candidates

    float tv[KNN] = {-FLT_MAX, -FLT_MAX, -FLT_MAX, -FLT_MAX};
    int   ti4[KNN] = {0x7fffffff, 0x7fffffff, 0x7fffffff, 0x7fffffff};
    const int base = s * C;
    for (int c = tid; c < C; c += 128)
        ins4(g_pv[base + c], g_pi[base + c], tv, ti4);

    __shared__ float sv[128 * KNN];
    __shared__ int   si[128 * KNN];
    __shared__ int   fidx[KNN];
#pragma unroll
    for (int q = 0; q < KNN; ++q) { sv[tid * KNN + q] = tv[q]; si[tid * KNN + q] = ti4[q]; }
    __syncthreads();

    if (tid == 0) {
        float fv[KNN] = {-FLT_MAX, -FLT_MAX, -FLT_MAX, -FLT_MAX};
        int   fi[KNN] = {0x7fffffff, 0x7fffffff, 0x7fffffff, 0x7fffffff};
        for (int c = 0; c < 128 * KNN; ++c) ins4(sv[c], si[c], fv, fi);
#pragma unroll
        for (int q = 0; q < KNN; ++q) fidx[q] = fi[q];
    }
    __syncthreads();

    const float4* r0 = reinterpret_cast<const float4*>(Bt + (size_t)fidx[0] * DDIM);
    const float4* r1 = reinterpret_cast<const float4*>(Bt + (size_t)fidx[1] * DDIM);
    const float4* r2 = reinterpret_cast<const float4*>(Bt + (size_t)fidx[2] * DDIM);
    const float4* r3 = reinterpret_cast<const float4*>(Bt + (size_t)fidx[3] * DDIM);
    float4* o = reinterpret_cast<float4*>(out + (size_t)s * DDIM);
#pragma unroll
    for (int it = 0; it < 2; ++it) {
        int u = tid + it * 128;
        float4 a = r0[u], b = r1[u], c = r2[u], d = r3[u];
        float4 r;
        r.x = (a.x + b.x + c.x + d.x) * 0.25f;
        r.y = (a.y + b.y + c.y + d.y) * 0.25f;
        r.z = (a.z + b.z + c.z + d.z) * 0.25f;
        r.w = (a.w + b.w + c.w + d.w) * 0.25f;
        o[u] = r;
    }
}

// ---------------------------------------------------------------------------
extern "C" void kernel_launch(void* const* d_in, const int* in_sizes, int n_in,
                              void* d_out, int out_size) {
    const float* src = (const float*)d_in[0];   // [2048, 1024]
    const float* tgt = (const float*)d_in[1];   // [50000, 1024]
    float* out = (float*)d_out;                 // [2048, 1024]

    row_norm_kernel<<<T_ROWS, 128>>>(tgt);
    gemm_topk_kernel<<<dim3(NT, MT), 256>>>(src, tgt);
    merge_kernel<<<S_ROWS, 128>>>(tgt, out);
}

// round 3
// speedup vs baseline: 4.2780x; 4.2780x over previous
#include <cuda_runtime.h>
#include <cuda_bf16.h>
#include <float.h>
#include <math.h>
#include <stdint.h>

#define S_ROWS 2048
#define T_ROWS 50000
#define DDIM   1024
#define KNN    4
#define BM     128
#define BN     128
#define BKS    64                      // k per stage (128B bf16 rows)
#define NSTG   (DDIM / BKS)            // 16
#define MT     (S_ROWS / BM)           // 16
#define NT     ((T_ROWS + BN - 1) / BN) // 391
#define RESC   8

#define STAGE_BYTES (BM * 128 + BN * 128)          // 32KB (A then B)
#define SMEM_BYTES  (BM * 132 * 4)                  // sims union: 67584 > 2*32768

// ---------------- device scratch ----------------
__device__ __nv_bfloat16 g_srcb[S_ROWS * DDIM];
__device__ __nv_bfloat16 g_tgtb[(size_t)T_ROWS * DDIM];   // pre-scaled by invnorm
__device__ float g_invn[T_ROWS];
__device__ float g_pv[S_ROWS * NT * KNN];
__device__ int   g_pi[S_ROWS * NT * KNN];

// ---------------- helpers ----------------
__device__ __forceinline__ uint32_t smem_to_u32(const void* p) {
    uint32_t a;
    asm("{ .reg .u64 t; cvta.to.shared.u64 t, %1; cvt.u32.u64 %0, t; }" : "=r"(a) : "l"(p));
    return a;
}
__device__ __forceinline__ void cp_async16(uint32_t dst, const void* src, uint32_t src_bytes) {
    asm volatile("cp.async.cg.shared.global [%0], [%1], 16, %2;\n"
                 :: "r"(dst), "l"(src), "r"(src_bytes) : "memory");
}
__device__ __forceinline__ void cp_commit() {
    asm volatile("cp.async.commit_group;\n" ::: "memory");
}
template <int N>
__device__ __forceinline__ void cp_wait() {
    asm volatile("cp.async.wait_group %0;\n" :: "n"(N) : "memory");
}
__device__ __forceinline__ void ldsm_x4(uint32_t addr, uint32_t& r0, uint32_t& r1,
                                        uint32_t& r2, uint32_t& r3) {
    asm volatile("ldmatrix.sync.aligned.m8n8.x4.shared.b16 {%0,%1,%2,%3}, [%4];\n"
                 : "=r"(r0), "=r"(r1), "=r"(r2), "=r"(r3) : "r"(addr));
}
__device__ __forceinline__ void mma16816(float& c0, float& c1, float& c2, float& c3,
                                         uint32_t a0, uint32_t a1, uint32_t a2, uint32_t a3,
                                         uint32_t b0, uint32_t b1) {
    asm volatile("mma.sync.aligned.m16n8k16.row.col.f32.bf16.bf16.f32 "
                 "{%0,%1,%2,%3}, {%4,%5,%6,%7}, {%8,%9}, {%0,%1,%2,%3};\n"
                 : "+f"(c0), "+f"(c1), "+f"(c2), "+f"(c3)
                 : "r"(a0), "r"(a1), "r"(a2), "r"(a3), "r"(b0), "r"(b1));
}

__device__ __forceinline__ bool better(float v, int i, float v2, int i2) {
    return (v > v2) || (v == v2 && i < i2);
}
template <int L>
__device__ __forceinline__ void insL(float v, int i, float* tv, int* ti) {
    if (!better(v, i, tv[L - 1], ti[L - 1])) return;
    tv[L - 1] = v; ti[L - 1] = i;
#pragma unroll
    for (int q = L - 1; q > 0; --q) {
        if (better(tv[q], ti[q], tv[q - 1], ti[q - 1])) {
            float fv = tv[q]; tv[q] = tv[q - 1]; tv[q - 1] = fv;
            int fi = ti[q]; ti[q] = ti[q - 1]; ti[q - 1] = fi;
        }
    }
}
__device__ __forceinline__ uint32_t pack_bf2(float a, float b) {
    __nv_bfloat162 h = __floats2bfloat162_rn(a, b);
    return *reinterpret_cast<uint32_t*>(&h);
}

// ---------------------------------------------------------------------------
// Kernel 1: target norms + scaled bf16 copy
// ---------------------------------------------------------------------------
__global__ void prep_tgt_kernel(const float* __restrict__ Bt) {
    const int t = blockIdx.x, tid = threadIdx.x;
    const float4* row = reinterpret_cast<const float4*>(Bt + (size_t)t * DDIM);
    float4 v0 = row[tid * 2], v1 = row[tid * 2 + 1];
    float s = v0.x * v0.x + v0.y * v0.y + v0.z * v0.z + v0.w * v0.w +
              v1.x * v1.x + v1.y * v1.y + v1.z * v1.z + v1.w * v1.w;
#pragma unroll
    for (int o = 16; o > 0; o >>= 1) s += __shfl_down_sync(0xffffffffu, s, o);
    __shared__ float ws[4];
    __shared__ float s_inv;
    int lane = tid & 31, w = tid >> 5;
    if (lane == 0) ws[w] = s;
    __syncthreads();
    if (tid == 0) {
        float inv = 1.f / fmaxf(sqrtf(ws[0] + ws[1] + ws[2] + ws[3]), 1e-8f);
        g_invn[t] = inv;
        s_inv = inv;
    }
    __syncthreads();
    float inv = s_inv;
    uint4 o;
    o.x = pack_bf2(v0.x * inv, v0.y * inv);
    o.y = pack_bf2(v0.z * inv, v0.w * inv);
    o.z = pack_bf2(v1.x * inv, v1.y * inv);
    o.w = pack_bf2(v1.z * inv, v1.w * inv);
    *reinterpret_cast<uint4*>(g_tgtb + (size_t)t * DDIM + tid * 8) = o;
}

__global__ void prep_src_kernel(const float* __restrict__ A) {
    const int t = blockIdx.x, tid = threadIdx.x;
    const float4* row = reinterpret_cast<const float4*>(A + (size_t)t * DDIM);
    float4 v0 = row[tid * 2], v1 = row[tid * 2 + 1];
    uint4 o;
    o.x = pack_bf2(v0.x, v0.y);
    o.y = pack_bf2(v0.z, v0.w);
    o.z = pack_bf2(v1.x, v1.y);
    o.w = pack_bf2(v1.z, v1.w);
    *reinterpret_cast<uint4*>(g_srcb + (size_t)t * DDIM + tid * 8) = o;
}

// ---------------------------------------------------------------------------
// Kernel 2: coarse bf16 GEMM via mma.sync (128x128 per CTA, K=1024) + top4/tile
// ---------------------------------------------------------------------------
__global__ __launch_bounds__(256, 2)
void coarse_gemm_topk() {
    extern __shared__ char smem[];
    const uint32_t sb = smem_to_u32(smem);
    const int tid = threadIdx.x;
    const int lane = tid & 31;
    const int w = tid >> 5;
    const int wm = w >> 1;          // 0..3
    const int wn = w & 1;           // 0..1
    const int m0 = blockIdx.x * BM;
    const int n0 = blockIdx.y * BN;

    // loader mapping: 1024 16B-chunks per operand / 256 threads = 4 each
    const int lrow = tid >> 1;                  // 0..127
    const int lc0  = (tid & 1) << 2;            // 0 or 4 (chunks within row)
    const __nv_bfloat16* Ag = g_srcb + (size_t)(m0 + lrow) * DDIM + lc0 * 8;
    const int tr = n0 + lrow;
    const __nv_bfloat16* Bg = g_tgtb + (size_t)min(tr, T_ROWS - 1) * DDIM + lc0 * 8;
    const uint32_t bsz = (tr < T_ROWS) ? 16u : 0u;
    // swizzled smem write offsets for the 4 chunks of this thread
    uint32_t awoff[4], bwoff[4];
#pragma unroll
    for (int i = 0; i < 4; ++i) {
        int c = lc0 + i;
        awoff[i] = (uint32_t)(lrow * 128 + ((c ^ (lrow & 7)) << 4));
        bwoff[i] = (uint32_t)(BM * 128 + lrow * 128 + ((c ^ (lrow & 7)) << 4));
    }

    float acc[2][8][4];
#pragma unroll
    for (int mi = 0; mi < 2; ++mi)
#pragma unroll
        for (int ni = 0; ni < 8; ++ni)
#pragma unroll
            for (int q = 0; q < 4; ++q) acc[mi][ni][q] = 0.f;

    // ldmatrix per-lane address components
    const int lrow8 = (lane & 7) + ((lane >> 3) & 1) * 8;   // row within 16
    const int khalf = (lane >> 4) & 1;                      // k half (0/1)
    int arowA[2], browB[4];
#pragma unroll
    for (int mi = 0; mi < 2; ++mi) arowA[mi] = wm * 32 + mi * 16 + lrow8;
#pragma unroll
    for (int nj = 0; nj < 4; ++nj) browB[nj] = wn * 64 + nj * 16 + lrow8;

    // prologue: stage 0
#pragma unroll
    for (int i = 0; i < 4; ++i) {
        cp_async16(sb + awoff[i], Ag + i * 8, 16u);
        cp_async16(sb + bwoff[i], Bg + i * 8, bsz);
    }
    cp_commit();

#pragma unroll 1
    for (int s = 0; s < NSTG; ++s) {
        if (s + 1 < NSTG) {
            const uint32_t nb = sb + ((s + 1) & 1) * STAGE_BYTES;
            const int ko = (s + 1) * BKS;
#pragma unroll
            for (int i = 0; i < 4; ++i) {
                cp_async16(nb + awoff[i], Ag + ko + i * 8, 16u);
                cp_async16(nb + bwoff[i], Bg + ko + i * 8, bsz);
            }
            cp_commit();
            cp_wait<1>();
        } else {
            cp_wait<0>();
        }
        __syncthreads();

        const uint32_t ab = sb + (s & 1) * STAGE_BYTES;
        const uint32_t bb = ab + BM * 128;
#pragma unroll
        for (int kk = 0; kk < 4; ++kk) {
            // A fragments: two 16x16 m-tiles
            uint32_t a[2][4];
#pragma unroll
            for (int mi = 0; mi < 2; ++mi) {
                int r = arowA[mi];
                uint32_t addr = ab + r * 128 + (((kk * 2 + khalf) ^ (r & 7)) << 4);
                ldsm_x4(addr, a[mi][0], a[mi][1], a[mi][2], a[mi][3]);
            }
            // B fragments + mma, 4 groups of 16 n
#pragma unroll
            for (int nj = 0; nj < 4; ++nj) {
                int r = browB[nj];
                uint32_t addr = bb + r * 128 + (((kk * 2 + khalf) ^ (r & 7)) << 4);
                uint32_t r0, r1, r2, r3;
                ldsm_x4(addr, r0, r1, r2, r3);
#pragma unroll
                for (int mi = 0; mi < 2; ++mi) {
                    mma16816(acc[mi][nj * 2][0], acc[mi][nj * 2][1],
                             acc[mi][nj * 2][2], acc[mi][nj * 2][3],
                             a[mi][0], a[mi][1], a[mi][2], a[mi][3], r0, r2);
                    mma16816(acc[mi][nj * 2 + 1][0], acc[mi][nj * 2 + 1][1],
                             acc[mi][nj * 2 + 1][2], acc[mi][nj * 2 + 1][3],
                             a[mi][0], a[mi][1], a[mi][2], a[mi][3], r1, r3);
                }
            }
        }
        __syncthreads();
    }

    // ---- epilogue: fragments -> smem sims [128][132], then per-row top-4
    float* sims = reinterpret_cast<float*>(smem);
#pragma unroll
    for (int mi = 0; mi < 2; ++mi) {
        const int r = wm * 32 + mi * 16 + (lane >> 2);
#pragma unroll
        for (int ni = 0; ni < 8; ++ni) {
            const int c = wn * 64 + ni * 8 + (lane & 3) * 2;
            *reinterpret_cast<float2*>(sims + r * 132 + c) =
                make_float2(acc[mi][ni][0], acc[mi][ni][1]);
            *reinterpret_cast<float2*>(sims + (r + 8) * 132 + c) =
                make_float2(acc[mi][ni][2], acc[mi][ni][3]);
        }
    }
    __syncthreads();

    if (tid < BM) {
        float tv[KNN] = {-FLT_MAX, -FLT_MAX, -FLT_MAX, -FLT_MAX};
        int   ti4[KNN] = {0x7fffffff, 0x7fffffff, 0x7fffffff, 0x7fffffff};
        const float* rowp = sims + tid * 132;
        const int nmax = min(BN, T_ROWS - n0);
        for (int c = 0; c < nmax; ++c) insL<KNN>(rowp[c], n0 + c, tv, ti4);
        const int m = m0 + tid;
        const int base = (m * NT + blockIdx.y) * KNN;
#pragma unroll
        for (int q = 0; q < KNN; ++q) { g_pv[base + q] = tv[q]; g_pi[base + q] = ti4[q]; }
    }
}

// ---------------------------------------------------------------------------
// Kernel 3: merge -> coarse top-8 -> exact fp32 rescore -> top-4 -> mean
// ---------------------------------------------------------------------------
__global__ __launch_bounds__(256)
void merge_rescore_kernel(const float* __restrict__ A, const float* __restrict__ Bt,
                          float* __restrict__ out) {
    const int s = blockIdx.x;
    const int tid = threadIdx.x;
    const int lane = tid & 31, warp = tid >> 5;
    const int C = NT * KNN;   // 1564

    __shared__ float sv[256 * KNN];
    __shared__ int   si[256 * KNN];
    __shared__ int   fi8[RESC];
    __shared__ float wsum[RESC * 8];
    __shared__ int   fidx[KNN];

    float tv[KNN] = {-FLT_MAX, -FLT_MAX, -FLT_MAX, -FLT_MAX};
    int   ti4[KNN] = {0x7fffffff, 0x7fffffff, 0x7fffffff, 0x7fffffff};
    const int base = s * C;
    for (int c = tid; c < C; c += 256)
        insL<KNN>(g_pv[base + c], g_pi[base + c], tv, ti4);
#pragma unroll
    for (int q = 0; q < KNN; ++q) { sv[tid * KNN + q] = tv[q]; si[tid * KNN + q] = ti4[q]; }
    __syncthreads();

    if (tid == 0) {
        float fv[RESC]; int fii[RESC];
#pragma unroll
        for (int q = 0; q < RESC; ++q) { fv[q] = -FLT_MAX; fii[q] = 0x7fffffff; }
        for (int c = 0; c < 256 * KNN; ++c) insL<RESC>(sv[c], si[c], fv, fii);
#pragma unroll
        for (int q = 0; q < RESC; ++q) fi8[q] = fii[q];
    }
    __syncthreads();

    const float4 sval = reinterpret_cast<const float4*>(A + (size_t)s * DDIM)[tid];
#pragma unroll 1
    for (int q = 0; q < RESC; ++q) {
        const int idx = fi8[q];
        float p = 0.f;
        if (idx < T_ROWS) {
            const float4 t4 = reinterpret_cast<const float4*>(Bt + (size_t)idx * DDIM)[tid];
            p = sval.x * t4.x + sval.y * t4.y + sval.z * t4.z + sval.w * t4.w;
        }
#pragma unroll
        for (int o = 16; o > 0; o >>= 1) p += __shfl_down_sync(0xffffffffu, p, o);
        if (lane == 0) wsum[q * 8 + warp] = p;
    }
    __syncthreads();

    if (tid == 0) {
        float fv[KNN] = {-FLT_MAX, -FLT_MAX, -FLT_MAX, -FLT_MAX};
        int   fii[KNN] = {0x7fffffff, 0x7fffffff, 0x7fffffff, 0x7fffffff};
#pragma unroll
        for (int q = 0; q < RESC; ++q) {
            const int idx = fi8[q];
            if (idx >= T_ROWS) continue;
            float tot = 0.f;
#pragma unroll
            for (int ww = 0; ww < 8; ++ww) tot += wsum[q * 8 + ww];
            insL<KNN>(tot * g_invn[idx], idx, fv, fii);
        }
#pragma unroll
        for (int q = 0; q < KNN; ++q) fidx[q] = fii[q];
    }
    __syncthreads();

    const float4 a = reinterpret_cast<const float4*>(Bt + (size_t)fidx[0] * DDIM)[tid];
    const float4 b = reinterpret_cast<const float4*>(Bt + (size_t)fidx[1] * DDIM)[tid];
    const float4 c = reinterpret_cast<const float4*>(Bt + (size_t)fidx[2] * DDIM)[tid];
    const float4 d = reinterpret_cast<const float4*>(Bt + (size_t)fidx[3] * DDIM)[tid];
    float4 r;
    r.x = (a.x + b.x + c.x + d.x) * 0.25f;
    r.y = (a.y + b.y + c.y + d.y) * 0.25f;
    r.z = (a.z + b.z + c.z + d.z) * 0.25f;
    r.w = (a.w + b.w + c.w + d.w) * 0.25f;
    reinterpret_cast<float4*>(out + (size_t)s * DDIM)[tid] = r;
}

// ---------------------------------------------------------------------------
extern "C" void kernel_launch(void* const* d_in, const int* in_sizes, int n_in,
                              void* d_out, int out_size) {
    const float* src = (const float*)d_in[0];   // [2048, 1024]
    const float* tgt = (const float*)d_in[1];   // [50000, 1024]
    float* out = (float*)d_out;                 // [2048, 1024]

    cudaFuncSetAttribute(coarse_gemm_topk,
                         cudaFuncAttributeMaxDynamicSharedMemorySize, SMEM_BYTES);

    prep_tgt_kernel<<<T_ROWS, 128>>>(tgt);
    prep_src_kernel<<<S_ROWS, 128>>>(src);
    coarse_gemm_topk<<<dim3(MT, NT), 256, SMEM_BYTES>>>();
    merge_rescore_kernel<<<S_ROWS, 256>>>(src, tgt, out);
}